// round 4
// baseline (speedup 1.0000x reference)
#include <cuda_runtime.h>

#define BATCH 4
#define DH 1024
#define DW 1024
#define FH 2048
#define FW 2048

// Scratch (device globals — no allocations allowed in kernel_launch)
__device__ float2 g_Y[BATCH * DH * DW];   // ifft_w(nnline_input)              32 MB
__device__ float2 g_Z[BATCH * FH * DW];   // ifft_h,2048(input * s)            64 MB
__device__ float2 g_S[BATCH * DW];        // per-column unit phase * 1/FH
__device__ float2 g_TW[1024];             // master twiddle: e^{-i*pi*j/1024}

__device__ __forceinline__ float2 cmul(float2 a, float2 b) {
    return make_float2(a.x * b.x - a.y * b.y, a.x * b.y + a.y * b.x);
}

__global__ void twiddle_init_kernel() {
    int j = blockIdx.x * blockDim.x + threadIdx.x;
    if (j < 1024) {
        float s, c;
        sincospif(j * (1.0f / 1024.0f), &s, &c);   // angle = pi*j/1024 = 2*pi*j/2048
        g_TW[j] = make_float2(c, -s);              // e^{-i*2pi*j/2048}
    }
}

__global__ void zero_fill_kernel(float* p, long long n) {
    long long i = (long long)blockIdx.x * blockDim.x + threadIdx.x;
    if (i < n) p[i] = 0.0f;
}

template <int NT>
__device__ __forceinline__ void load_tw(float2* stw) {
    for (int i = threadIdx.x; i < 1024; i += NT) stw[i] = g_TW[i];
}

// Stockham radix-2 autosort FFT over NCOL interleaved columns.
// Layout: buf[point * NCOL + col]. Returns pointer holding the result.
template <int N, int NCOL, bool INV, int NT>
__device__ float2* stockham_fft(float2* buf0, float2* buf1, const float2* tw) {
    float2* src = buf0;
    float2* dst = buf1;
#pragma unroll 1
    for (int p = 1; p < N; p <<= 1) {
        const int tstep = 1024 / p;  // e^{-i*pi*k/p} = tw[k*1024/p]
        for (int it = threadIdx.x; it < (N / 2) * NCOL; it += NT) {
            int c = it & (NCOL - 1);
            int j = it / NCOL;
            int k = j & (p - 1);
            float2 a = src[j * NCOL + c];
            float2 b = src[(j + N / 2) * NCOL + c];
            float2 w = tw[k * tstep];
            if (INV) w.y = -w.y;
            b = cmul(b, w);
            int jd = ((j - k) << 1) + k;
            dst[jd * NCOL + c]       = make_float2(a.x + b.x, a.y + b.y);
            dst[(jd + p) * NCOL + c] = make_float2(a.x - b.x, a.y - b.y);
        }
        __syncthreads();
        float2* t = src; src = dst; dst = t;
    }
    return src;
}

// K1: Y[row,:] = ifft_1024(nnline_input[row,:])
__global__ void k1_row_ifft(const float* __restrict__ nn_in) {
    __shared__ float2 stw[1024];
    __shared__ float2 sbuf[2 * 1024];
    const int row = blockIdx.x;
    load_tw<256>(stw);
    const float* in = nn_in + (size_t)row * DW;
    for (int j = threadIdx.x; j < DW; j += 256)
        sbuf[j] = make_float2(in[j] * (1.0f / DW), 0.0f);
    __syncthreads();
    float2* res = stockham_fft<1024, 1, true, 256>(sbuf, sbuf + 1024, stw);
    float2* out = g_Y + (size_t)row * DW;
    for (int j = threadIdx.x; j < DW; j += 256) out[j] = res[j];
}

// K2: fft_1024 over Y columns; dot with input; store unit phase / FH.
__global__ void k2_col_fft_dot(const float* __restrict__ input) {
    extern __shared__ float2 sm[];
    float2* stw  = sm;                 // 1024
    float2* buf0 = sm + 1024;          // 4*1024
    float2* buf1 = buf0 + 4 * 1024;    // 4*1024
    const int bg = blockIdx.x;
    const int b  = bg >> 8;
    const int w0 = (bg & 255) << 2;
    load_tw<256>(stw);
    const float2* Yp = g_Y + (size_t)b * DH * DW + w0;
    for (int it = threadIdx.x; it < DH * 4; it += 256) {
        int c = it & 3, h = it >> 2;
        buf0[it] = Yp[(size_t)h * DW + c];
    }
    __syncthreads();
    float2* res = stockham_fft<1024, 4, false, 256>(buf0, buf1, stw);

    const float* Xp = input + (size_t)b * DH * DW + w0;
    float2 acc = make_float2(0.0f, 0.0f);
    for (int it = threadIdx.x; it < DH * 4; it += 256) {
        int c = it & 3, h = it >> 2;
        float x  = Xp[(size_t)h * DW + c];
        float2 s = res[it];
        acc.x += s.x * x;
        acc.y -= s.y * x;
    }
    float2* part = buf1;
    __syncthreads();
    part[threadIdx.x] = acc;
    __syncthreads();
    for (int s = 128; s >= 4; s >>= 1) {
        if (threadIdx.x < s) {
            part[threadIdx.x].x += part[threadIdx.x + s].x;
            part[threadIdx.x].y += part[threadIdx.x + s].y;
        }
        __syncthreads();
    }
    if (threadIdx.x < 4) {
        float2 t = part[threadIdx.x];
        float r  = sqrtf(t.x * t.x + t.y * t.y);
        float2 sc = (r > 0.0f) ? make_float2(t.y / r, t.x / r) : make_float2(1.0f, 0.0f);
        g_S[b * DW + w0 + threadIdx.x] = make_float2(sc.x * (1.0f / FH), sc.y * (1.0f / FH));
    }
}

// K4: Z[:,w] = ifft_2048( zero-pad( input[:,w] * s[w] ) )
__global__ void __launch_bounds__(512, 1) k4_col_ifft(const float* __restrict__ input) {
    extern __shared__ float2 sm[];
    float2* stw  = sm;                 // 1024
    float2* buf0 = sm + 1024;          // 4*2048
    float2* buf1 = buf0 + 4 * 2048;    // 4*2048
    __shared__ float2 ssc[4];
    const int bg = blockIdx.x;
    const int b  = bg >> 8;
    const int w0 = (bg & 255) << 2;
    load_tw<512>(stw);
    if (threadIdx.x < 4) ssc[threadIdx.x] = g_S[b * DW + w0 + threadIdx.x];
    __syncthreads();
    const float* Xp = input + (size_t)b * DH * DW + w0;
    for (int it = threadIdx.x; it < FH * 4; it += 512) {
        int c = it & 3, h = it >> 2;
        float2 v = make_float2(0.0f, 0.0f);
        if (h < DH) {
            float x = Xp[(size_t)h * DW + c];
            v = make_float2(x * ssc[c].x, x * ssc[c].y);
        }
        buf0[it] = v;
    }
    __syncthreads();
    float2* res = stockham_fft<2048, 4, true, 512>(buf0, buf1, stw);
    float2* Zp = g_Z + (size_t)b * FH * DW + w0;
    for (int it = threadIdx.x; it < FH * 4; it += 512) {
        int c = it & 3, m = it >> 2;
        Zp[(size_t)m * DW + c] = res[it];
    }
}

// K5: R = fft_2048( zero-pad(Z row) ); epilogue. COMPLEX_OUT selects write format.
template <bool COMPLEX_OUT>
__global__ void __launch_bounds__(512) k5_row_fft_out(const float* __restrict__ nn_out,
                                                      const float* __restrict__ multi_out,
                                                      float* __restrict__ out) {
    __shared__ float2 stw[1024];
    __shared__ float2 sbuf[2 * 2048];
    const int row = blockIdx.x;  // 0 .. BATCH*FH-1
    load_tw<512>(stw);
    const float2* Zp = g_Z + (size_t)row * DW;
    for (int j = threadIdx.x; j < FW; j += 512)
        sbuf[j] = (j < DW) ? Zp[j] : make_float2(0.0f, 0.0f);
    __syncthreads();
    float2* res = stockham_fft<2048, 1, false, 512>(sbuf, sbuf + 2048, stw);
    const float* ap = nn_out    + (size_t)row * FW;
    const float* mp = multi_out + (size_t)row * FW;
    const float inv = 1.0f / 1.1f;  // 1/(1+RHO)
    if (COMPLEX_OUT) {
        float2* op = (float2*)out + (size_t)row * FW;
        for (int j = threadIdx.x; j < FW; j += 512) {
            float mn = ap[j] - mp[j];
            float2 r = res[j];
            op[j] = make_float2(mn - (mn - r.x) * inv, r.y * inv);
        }
    } else {
        float* op = out + (size_t)row * FW;
        for (int j = threadIdx.x; j < FW; j += 512) {
            float mn = ap[j] - mp[j];
            op[j] = mn - (mn - res[j].x) * inv;
        }
    }
}

extern "C" void kernel_launch(void* const* d_in, const int* in_sizes, int n_in,
                              void* d_out, int out_size) {
    // ---- Input identification, unit-agnostic (elements OR bytes):
    // frame tensors have size == 4 * data tensor size in either unit.
    const float* frames[4] = {0, 0, 0, 0};
    const float* datas[4]  = {0, 0, 0, 0};
    int nf = 0, nd = 0;
    int first_is_frame = 0;
    long long mx = 0, mn = 0x7fffffffffffffffLL;
    for (int i = 0; i < n_in; i++) {
        long long s = in_sizes[i];
        if (s > mx) mx = s;
        if (s < mn) mn = s;
    }
    int ok = (n_in == 4) && (mx == 4 * mn) && (mn > 0);
    if (ok) {
        for (int i = 0; i < 4; i++) {
            if ((long long)in_sizes[i] == mx) { if (i == 0) first_is_frame = 1; if (nf < 4) frames[nf++] = (const float*)d_in[i]; }
            else if ((long long)in_sizes[i] == mn) { if (nd < 4) datas[nd++] = (const float*)d_in[i]; }
        }
        ok = (nf == 2 && nd == 2);
    }

    // Output format: 33554432 (float-pair elems) / 134217728 (bytes) => interleaved complex.
    // Anything else (incl. ambiguous 16777216) => real-part-only floats (safe lower bound).
    long long osz = out_size;
    bool complex_out = (osz == 2LL * BATCH * FH * FW) || (osz == 8LL * BATCH * FH * FW);

    if (!ok) {
        // Could not identify inputs: produce a defined (wrong) output without any
        // unverified dereference. 16M floats <= every candidate buffer size.
        long long n = (long long)BATCH * FH * FW;
        zero_fill_kernel<<<(int)((n + 511) / 512), 512>>>((float*)d_out, n);
        return;
    }

    const float* input  = datas[0];
    const float* nn_in  = datas[1];
    const float* nn_out = first_is_frame ? frames[0] : frames[1];  // dict vs alphabetical
    const float* multi  = first_is_frame ? frames[1] : frames[0];

    const size_t smem_k2 = (size_t)(1024 + 2 * 4 * 1024) * sizeof(float2);  //  73728 B
    const size_t smem_k4 = (size_t)(1024 + 2 * 4 * 2048) * sizeof(float2);  // 139264 B
    cudaFuncSetAttribute(k2_col_fft_dot, cudaFuncAttributeMaxDynamicSharedMemorySize, (int)smem_k2);
    cudaFuncSetAttribute(k4_col_ifft,    cudaFuncAttributeMaxDynamicSharedMemorySize, (int)smem_k4);

    twiddle_init_kernel<<<4, 256>>>();
    k1_row_ifft<<<BATCH * DH, 256>>>(nn_in);
    k2_col_fft_dot<<<BATCH * (DW / 4), 256, smem_k2>>>(input);
    k4_col_ifft<<<BATCH * (DW / 4), 512, smem_k4>>>(input);
    if (complex_out)
        k5_row_fft_out<true><<<BATCH * FH, 512>>>(nn_out, multi, (float*)d_out);
    else
        k5_row_fft_out<false><<<BATCH * FH, 512>>>(nn_out, multi, (float*)d_out);
}

// round 5
// speedup vs baseline: 1.8546x; 1.8546x over previous
#include <cuda_runtime.h>

#define BATCH 4
#define DH 1024
#define DW 1024
#define FH 2048
#define FW 2048

// Scratch (device globals — no allocations allowed in kernel_launch)
__device__ float2 g_Y[BATCH * DH * DW];   // ifft_w(nnline_input)              32 MB
__device__ float2 g_Z[BATCH * FH * DW];   // ifft_h,2048(input * s)            64 MB
__device__ float2 g_S[BATCH * DW];        // per-column unit phase * 1/FH
__device__ float2 g_TW[512];              // tw[j] = e^{-2pi i j/2048}, j<512

__device__ __forceinline__ float2 cmul(float2 a, float2 b) {
    return make_float2(a.x * b.x - a.y * b.y, a.x * b.y + a.y * b.x);
}

__global__ void twiddle_init_kernel() {
    int j = blockIdx.x * blockDim.x + threadIdx.x;
    if (j < 512) {
        float s, c;
        sincospif(j * (1.0f / 1024.0f), &s, &c);   // pi*j/1024 = 2pi*j/2048
        g_TW[j] = make_float2(c, -s);
    }
}

__global__ void zero_fill_kernel(float* p, long long n) {
    long long i = (long long)blockIdx.x * blockDim.x + threadIdx.x;
    if (i < n) p[i] = 0.0f;
}

template <int NT>
__device__ __forceinline__ void load_tw(float2* stw) {
    for (int i = threadIdx.x; i < 512; i += NT) stw[i] = g_TW[i];
}

// Stockham radix-4 autosort FFT over NCOL interleaved columns.
// Requires N/P0 to be a power of 4. tw[j] = e^{-2pi i j/2048} (j<512).
// Stage twiddle: w1 = e^{-2pi i k/(4p)} = tw[k*512/p], k<p, p<=512.
template <int N, int NCOL, bool INV, int NT, int P0>
__device__ float2* stockham_fft4(float2* buf0, float2* buf1, const float2* tw) {
    float2* src = buf0;
    float2* dst = buf1;
    constexpr int NB = (N / 4) * NCOL;  // butterflies per stage
#pragma unroll 1
    for (int p = P0; p < N; p <<= 2) {
        const int tws = 512 / p;
#pragma unroll
        for (int u = 0; u < NB / NT; u++) {
            int it = threadIdx.x + u * NT;
            int c = (NCOL == 1) ? 0 : (it & (NCOL - 1));
            int j = (NCOL == 1) ? it : (it / NCOL);
            int k = j & (p - 1);
            float2 a0 = src[j * NCOL + c];
            float2 a1 = src[(j + N / 4) * NCOL + c];
            float2 a2 = src[(j + N / 2) * NCOL + c];
            float2 a3 = src[(j + 3 * (N / 4)) * NCOL + c];
            float2 w1 = tw[k * tws];
            if (INV) w1.y = -w1.y;
            float2 w2 = cmul(w1, w1);
            float2 w3 = cmul(w2, w1);
            a1 = cmul(a1, w1);
            a2 = cmul(a2, w2);
            a3 = cmul(a3, w3);
            float2 s0 = make_float2(a0.x + a2.x, a0.y + a2.y);
            float2 s1 = make_float2(a0.x - a2.x, a0.y - a2.y);
            float2 s2 = make_float2(a1.x + a3.x, a1.y + a3.y);
            float2 s3 = make_float2(a1.x - a3.x, a1.y - a3.y);
            float2 c0 = make_float2(s0.x + s2.x, s0.y + s2.y);
            float2 c2 = make_float2(s0.x - s2.x, s0.y - s2.y);
            float2 c1, c3;
            if (!INV) {  // c1 = s1 - i*s3 ; c3 = s1 + i*s3
                c1 = make_float2(s1.x + s3.y, s1.y - s3.x);
                c3 = make_float2(s1.x - s3.y, s1.y + s3.x);
            } else {     // inverse: +i
                c1 = make_float2(s1.x - s3.y, s1.y + s3.x);
                c3 = make_float2(s1.x + s3.y, s1.y - s3.x);
            }
            int jd = ((j - k) << 2) + k;
            dst[jd * NCOL + c]           = c0;
            dst[(jd + p) * NCOL + c]     = c1;
            dst[(jd + 2 * p) * NCOL + c] = c2;
            dst[(jd + 3 * p) * NCOL + c] = c3;
        }
        __syncthreads();
        float2* t = src; src = dst; dst = t;
    }
    return src;
}

// K1: Y[row,:] = ifft_1024(nnline_input[row,:])
__global__ void k1_row_ifft(const float* __restrict__ nn_in) {
    __shared__ float2 stw[512];
    __shared__ float2 sbuf[2 * 1024];
    const int row = blockIdx.x;
    load_tw<256>(stw);
    const float* in = nn_in + (size_t)row * DW;
    for (int j = threadIdx.x; j < DW; j += 256)
        sbuf[j] = make_float2(in[j] * (1.0f / DW), 0.0f);
    __syncthreads();
    float2* res = stockham_fft4<1024, 1, true, 256, 1>(sbuf, sbuf + 1024, stw);
    float2* out = g_Y + (size_t)row * DW;
    for (int j = threadIdx.x; j < DW; j += 256) out[j] = res[j];
}

// K2: fft_1024 over Y columns; dot with input; store unit phase / FH.
__global__ void k2_col_fft_dot(const float* __restrict__ input) {
    extern __shared__ float2 sm[];
    float2* stw  = sm;                 // 512
    float2* buf0 = sm + 512;           // 4*1024
    float2* buf1 = buf0 + 4 * 1024;    // 4*1024
    const int bg = blockIdx.x;
    const int b  = bg >> 8;
    const int w0 = (bg & 255) << 2;
    load_tw<256>(stw);
    const float2* Yp = g_Y + (size_t)b * DH * DW + w0;
    for (int it = threadIdx.x; it < DH * 4; it += 256) {
        int c = it & 3, h = it >> 2;
        buf0[it] = Yp[(size_t)h * DW + c];
    }
    __syncthreads();
    float2* res = stockham_fft4<1024, 4, false, 256, 1>(buf0, buf1, stw);
    float2* part = (res == buf0) ? buf1 : buf0;   // non-result buffer as scratch

    const float* Xp = input + (size_t)b * DH * DW + w0;
    float2 acc = make_float2(0.0f, 0.0f);
    for (int it = threadIdx.x; it < DH * 4; it += 256) {
        int c = it & 3, h = it >> 2;
        float x  = Xp[(size_t)h * DW + c];
        float2 s = res[it];
        acc.x += s.x * x;
        acc.y -= s.y * x;
    }
    __syncthreads();
    part[threadIdx.x] = acc;
    __syncthreads();
    for (int s = 128; s >= 4; s >>= 1) {
        if (threadIdx.x < s) {
            part[threadIdx.x].x += part[threadIdx.x + s].x;
            part[threadIdx.x].y += part[threadIdx.x + s].y;
        }
        __syncthreads();
    }
    if (threadIdx.x < 4) {
        float2 t = part[threadIdx.x];
        float r  = sqrtf(t.x * t.x + t.y * t.y);
        float2 sc = (r > 0.0f) ? make_float2(t.y / r, t.x / r) : make_float2(1.0f, 0.0f);
        g_S[b * DW + w0 + threadIdx.x] = make_float2(sc.x * (1.0f / FH), sc.y * (1.0f / FH));
    }
}

// K4: Z[:,w] = ifft_2048( zero-pad( input[:,w] * s[w] ) ), 4 cols/block.
// First radix-2 stage of the padded ifft is pure duplication -> folded into load.
__global__ void __launch_bounds__(512, 1) k4_col_ifft(const float* __restrict__ input) {
    extern __shared__ float2 sm[];
    float2* stw  = sm;                 // 512
    float2* buf0 = sm + 512;           // 4*2048
    float2* buf1 = buf0 + 4 * 2048;    // 4*2048
    __shared__ float2 ssc[4];
    const int bg = blockIdx.x;
    const int b  = bg >> 8;
    const int w0 = (bg & 255) << 2;
    load_tw<512>(stw);
    if (threadIdx.x < 4) ssc[threadIdx.x] = g_S[b * DW + w0 + threadIdx.x];
    __syncthreads();
    const float* Xp = input + (size_t)b * DH * DW + w0;
    for (int it = threadIdx.x; it < DH * 4; it += 512) {
        int c = it & 3, h = it >> 2;
        float x = Xp[(size_t)h * DW + c];
        float2 v = make_float2(x * ssc[c].x, x * ssc[c].y);
        buf0[(2 * h) * 4 + c]     = v;   // stage p=1 on zero-padded data = duplication
        buf0[(2 * h + 1) * 4 + c] = v;
    }
    __syncthreads();
    float2* res = stockham_fft4<2048, 4, true, 512, 2>(buf0, buf1, stw);
    float2* Zp = g_Z + (size_t)b * FH * DW + w0;
    for (int it = threadIdx.x; it < FH * 4; it += 512) {
        int c = it & 3, m = it >> 2;
        Zp[(size_t)m * DW + c] = res[it];
    }
}

// K5: R = fft_2048( zero-pad(Z row) ); epilogue. First stage folded into load.
template <bool COMPLEX_OUT>
__global__ void __launch_bounds__(512) k5_row_fft_out(const float* __restrict__ nn_out,
                                                      const float* __restrict__ multi_out,
                                                      float* __restrict__ out) {
    __shared__ float2 stw[512];
    __shared__ float2 sbuf[2 * 2048];
    const int row = blockIdx.x;  // 0 .. BATCH*FH-1
    load_tw<512>(stw);
    const float2* Zp = g_Z + (size_t)row * DW;
    for (int j = threadIdx.x; j < DW; j += 512) {
        float2 v = Zp[j];
        sbuf[2 * j]     = v;   // stage p=1 on zero-padded data = duplication
        sbuf[2 * j + 1] = v;
    }
    __syncthreads();
    float2* res = stockham_fft4<2048, 1, false, 512, 2>(sbuf, sbuf + 2048, stw);
    const float* ap = nn_out    + (size_t)row * FW;
    const float* mp = multi_out + (size_t)row * FW;
    const float inv = 1.0f / 1.1f;  // 1/(1+RHO)
    if (COMPLEX_OUT) {
        float2* op = (float2*)out + (size_t)row * FW;
        for (int j = threadIdx.x; j < FW; j += 512) {
            float mn = ap[j] - mp[j];
            float2 r = res[j];
            op[j] = make_float2(mn - (mn - r.x) * inv, r.y * inv);
        }
    } else {
        float* op = out + (size_t)row * FW;
        for (int j = threadIdx.x; j < FW; j += 512) {
            float mn = ap[j] - mp[j];
            op[j] = mn - (mn - res[j].x) * inv;
        }
    }
}

extern "C" void kernel_launch(void* const* d_in, const int* in_sizes, int n_in,
                              void* d_out, int out_size) {
    // Input identification, unit-agnostic: frame tensors are 4x the data tensors.
    const float* frames[4] = {0, 0, 0, 0};
    const float* datas[4]  = {0, 0, 0, 0};
    int nf = 0, nd = 0;
    int first_is_frame = 0;
    long long mx = 0, mn = 0x7fffffffffffffffLL;
    for (int i = 0; i < n_in; i++) {
        long long s = in_sizes[i];
        if (s > mx) mx = s;
        if (s < mn) mn = s;
    }
    int ok = (n_in == 4) && (mx == 4 * mn) && (mn > 0);
    if (ok) {
        for (int i = 0; i < 4; i++) {
            if ((long long)in_sizes[i] == mx) { if (i == 0) first_is_frame = 1; if (nf < 4) frames[nf++] = (const float*)d_in[i]; }
            else if ((long long)in_sizes[i] == mn) { if (nd < 4) datas[nd++] = (const float*)d_in[i]; }
        }
        ok = (nf == 2 && nd == 2);
    }

    long long osz = out_size;
    bool complex_out = (osz == 2LL * BATCH * FH * FW) || (osz == 8LL * BATCH * FH * FW);

    if (!ok) {
        long long n = (long long)BATCH * FH * FW;
        zero_fill_kernel<<<(int)((n + 511) / 512), 512>>>((float*)d_out, n);
        return;
    }

    const float* input  = datas[0];
    const float* nn_in  = datas[1];
    const float* nn_out = first_is_frame ? frames[0] : frames[1];  // dict vs alphabetical
    const float* multi  = first_is_frame ? frames[1] : frames[0];

    const size_t smem_k2 = (size_t)(512 + 2 * 4 * 1024) * sizeof(float2);  //  69632 B
    const size_t smem_k4 = (size_t)(512 + 2 * 4 * 2048) * sizeof(float2);  // 135168 B
    cudaFuncSetAttribute(k2_col_fft_dot, cudaFuncAttributeMaxDynamicSharedMemorySize, (int)smem_k2);
    cudaFuncSetAttribute(k4_col_ifft,    cudaFuncAttributeMaxDynamicSharedMemorySize, (int)smem_k4);

    twiddle_init_kernel<<<2, 256>>>();
    k1_row_ifft<<<BATCH * DH, 256>>>(nn_in);
    k2_col_fft_dot<<<BATCH * (DW / 4), 256, smem_k2>>>(input);
    k4_col_ifft<<<BATCH * (DW / 4), 512, smem_k4>>>(input);
    if (complex_out)
        k5_row_fft_out<true><<<BATCH * FH, 512>>>(nn_out, multi, (float*)d_out);
    else
        k5_row_fft_out<false><<<BATCH * FH, 512>>>(nn_out, multi, (float*)d_out);
}

// round 6
// speedup vs baseline: 2.2488x; 1.2126x over previous
#include <cuda_runtime.h>

#define BATCH 4
#define DH 1024
#define DW 1024
#define FH 2048
#define FW 2048

// Scratch (device globals — no allocations allowed in kernel_launch)
__device__ float2 g_Y[BATCH * DH * DW];   // ifft_w(nnline_input)              32 MB
__device__ float2 g_Z[BATCH * FH * DW];   // ifft_h,2048(input * s)            64 MB
__device__ float2 g_S[BATCH * DW];        // per-column unit phase * 1/FH
__device__ float2 g_TW[512];              // tw[j] = e^{-2pi i j/2048}, j<512

__device__ __forceinline__ float2 cmul(float2 a, float2 b) {
    return make_float2(a.x * b.x - a.y * b.y, a.x * b.y + a.y * b.x);
}

__global__ void twiddle_init_kernel() {
    int j = blockIdx.x * blockDim.x + threadIdx.x;
    if (j < 512) {
        float s, c;
        sincospif(j * (1.0f / 1024.0f), &s, &c);   // pi*j/1024 = 2pi*j/2048
        g_TW[j] = make_float2(c, -s);
    }
}

__global__ void zero_fill_kernel(float* p, long long n) {
    long long i = (long long)blockIdx.x * blockDim.x + threadIdx.x;
    if (i < n) p[i] = 0.0f;
}

template <int NT>
__device__ __forceinline__ void load_tw(float2* stw) {
    for (int i = threadIdx.x; i < 512; i += NT) stw[i] = g_TW[i];
}

// Stockham radix-4 autosort FFT over NCOL interleaved columns.
// tw[j] = e^{-2pi i j/2048} (j<512). Stage twiddle w1 = tw[k*512/p].
template <int N, int NCOL, bool INV, int NT, int P0>
__device__ float2* stockham_fft4(float2* buf0, float2* buf1, const float2* tw) {
    float2* src = buf0;
    float2* dst = buf1;
    constexpr int NB = (N / 4) * NCOL;
#pragma unroll 1
    for (int p = P0; p < N; p <<= 2) {
        const int tws = 512 / p;
#pragma unroll
        for (int u = 0; u < NB / NT; u++) {
            int it = threadIdx.x + u * NT;
            int c = (NCOL == 1) ? 0 : (it & (NCOL - 1));
            int j = (NCOL == 1) ? it : (it / NCOL);
            int k = j & (p - 1);
            float2 a0 = src[j * NCOL + c];
            float2 a1 = src[(j + N / 4) * NCOL + c];
            float2 a2 = src[(j + N / 2) * NCOL + c];
            float2 a3 = src[(j + 3 * (N / 4)) * NCOL + c];
            float2 w1 = tw[k * tws];
            if (INV) w1.y = -w1.y;
            float2 w2 = cmul(w1, w1);
            float2 w3 = cmul(w2, w1);
            a1 = cmul(a1, w1);
            a2 = cmul(a2, w2);
            a3 = cmul(a3, w3);
            float2 s0 = make_float2(a0.x + a2.x, a0.y + a2.y);
            float2 s1 = make_float2(a0.x - a2.x, a0.y - a2.y);
            float2 s2 = make_float2(a1.x + a3.x, a1.y + a3.y);
            float2 s3 = make_float2(a1.x - a3.x, a1.y - a3.y);
            float2 c0 = make_float2(s0.x + s2.x, s0.y + s2.y);
            float2 c2 = make_float2(s0.x - s2.x, s0.y - s2.y);
            float2 c1, c3;
            if (!INV) {
                c1 = make_float2(s1.x + s3.y, s1.y - s3.x);
                c3 = make_float2(s1.x - s3.y, s1.y + s3.x);
            } else {
                c1 = make_float2(s1.x - s3.y, s1.y + s3.x);
                c3 = make_float2(s1.x + s3.y, s1.y - s3.x);
            }
            int jd = ((j - k) << 2) + k;
            dst[jd * NCOL + c]           = c0;
            dst[(jd + p) * NCOL + c]     = c1;
            dst[(jd + 2 * p) * NCOL + c] = c2;
            dst[(jd + 3 * p) * NCOL + c] = c3;
        }
        __syncthreads();
        float2* t = src; src = dst; dst = t;
    }
    return src;
}

// Hermitian unpack helpers: W = fft/ifft(xa + i*xb), xa,xb real.
// A[m] = (W[m]+conj(W[N-m]))/2 ; B[m] = -i(W[m]-conj(W[N-m]))/2
__device__ __forceinline__ float2 unpackA(float2 W, float2 Wm) {
    return make_float2(0.5f * (W.x + Wm.x), 0.5f * (W.y - Wm.y));
}
__device__ __forceinline__ float2 unpackB(float2 W, float2 Wm) {
    return make_float2(0.5f * (W.y + Wm.y), 0.5f * (Wm.x - W.x));
}

// K1: two real rows packed per complex ifft_1024.
__global__ void k1_row_ifft(const float* __restrict__ nn_in) {
    __shared__ float2 stw[512];
    __shared__ float2 sbuf[2 * 1024];
    const int row0 = 2 * blockIdx.x;      // 0 .. BATCH*DH-1 (pairs)
    load_tw<256>(stw);
    const float* ina = nn_in + (size_t)row0 * DW;
    const float* inb = ina + DW;
    for (int j = threadIdx.x; j < DW; j += 256)
        sbuf[j] = make_float2(ina[j] * (1.0f / DW), inb[j] * (1.0f / DW));
    __syncthreads();
    float2* res = stockham_fft4<1024, 1, true, 256, 1>(sbuf, sbuf + 1024, stw);
    float2* outa = g_Y + (size_t)row0 * DW;
    float2* outb = outa + DW;
    for (int j = threadIdx.x; j < DW; j += 256) {
        int jm = (1024 - j) & 1023;
        float2 W = res[j], Wm = res[jm];
        outa[j] = unpackA(W, Wm);
        outb[j] = unpackB(W, Wm);
    }
}

// K2: X = fft_1024(input cols, 2 real cols packed); T[w] = sum_m Y[m,w]*X[m,w];
// tmp = conj(T); scale = (tmp.im + i*tmp.re)/|tmp| = (-T.y + i*T.x)/|T|, * 1/FH.
__global__ void k2_col_fft_dot(const float* __restrict__ input) {
    __shared__ float2 stw[512];
    __shared__ float2 buf0[1024 * 2];
    __shared__ float2 buf1[1024 * 2];
    const int bg = blockIdx.x;
    const int b  = bg >> 8;
    const int w0 = (bg & 255) << 2;
    load_tw<256>(stw);
    const float* Xp = input + (size_t)b * DH * DW + w0;
    for (int it = threadIdx.x; it < DH * 2; it += 256) {
        int q = it & 1, h = it >> 1;
        float2 v = *(const float2*)(Xp + (size_t)h * DW + 2 * q);  // cols 2q,2q+1
        buf0[h * 2 + q] = v;
    }
    __syncthreads();
    float2* res = stockham_fft4<1024, 2, false, 256, 1>(buf0, buf1, stw);
    float2* part = (res == buf0) ? buf1 : buf0;

    const float2* Yp = g_Y + (size_t)b * DH * DW + w0;
    const int c = threadIdx.x & 3;
    const int q = c >> 1, e = c & 1;
    float2 acc = make_float2(0.0f, 0.0f);
    for (int m = threadIdx.x >> 2; m < DH; m += 64) {
        int mm = (1024 - m) & 1023;
        float2 W = res[m * 2 + q], Wm = res[mm * 2 + q];
        float2 X = e ? unpackB(W, Wm) : unpackA(W, Wm);
        float2 Yv = Yp[(size_t)m * DW + c];
        acc.x += Yv.x * X.x - Yv.y * X.y;
        acc.y += Yv.x * X.y + Yv.y * X.x;
    }
    __syncthreads();
    part[threadIdx.x] = acc;
    __syncthreads();
    for (int s = 128; s >= 4; s >>= 1) {
        if (threadIdx.x < s) {
            part[threadIdx.x].x += part[threadIdx.x + s].x;
            part[threadIdx.x].y += part[threadIdx.x + s].y;
        }
        __syncthreads();
    }
    if (threadIdx.x < 4) {
        float2 T = part[threadIdx.x];
        float r  = sqrtf(T.x * T.x + T.y * T.y);
        float2 sc = (r > 0.0f) ? make_float2(-T.y / r, T.x / r) : make_float2(1.0f, 0.0f);
        g_S[b * DW + w0 + threadIdx.x] = make_float2(sc.x * (1.0f / FH), sc.y * (1.0f / FH));
    }
}

// K4: 4 cols as 2 packed real ifft_2048 (zero-pad p=1 stage folded into load).
// Phase scale s applied AFTER Hermitian unpack (keeps FFT inputs real).
__global__ void __launch_bounds__(256) k4_col_ifft(const float* __restrict__ input) {
    extern __shared__ float2 sm[];
    float2* stw  = sm;                 // 512
    float2* buf0 = sm + 512;           // 2048*2
    float2* buf1 = buf0 + 2048 * 2;    // 2048*2
    __shared__ float2 ssc[4];
    const int bg = blockIdx.x;
    const int b  = bg >> 8;
    const int w0 = (bg & 255) << 2;
    load_tw<256>(stw);
    if (threadIdx.x < 4) ssc[threadIdx.x] = g_S[b * DW + w0 + threadIdx.x];
    __syncthreads();
    const float* Xp = input + (size_t)b * DH * DW + w0;
    for (int it = threadIdx.x; it < DH * 2; it += 256) {
        int q = it & 1, h = it >> 1;
        float2 v = *(const float2*)(Xp + (size_t)h * DW + 2 * q);
        buf0[(2 * h) * 2 + q]     = v;   // p=1 stage on zero-padded data = duplication
        buf0[(2 * h + 1) * 2 + q] = v;
    }
    __syncthreads();
    float2* res = stockham_fft4<2048, 2, true, 256, 2>(buf0, buf1, stw);
    float2* Zp = g_Z + (size_t)b * FH * DW + w0;
    for (int it = threadIdx.x; it < FH * 2; it += 256) {
        int q = it & 1, m = it >> 1;
        int mm = (2048 - m) & 2047;
        float2 W = res[m * 2 + q], Wm = res[mm * 2 + q];
        float2* zr = Zp + (size_t)m * DW + 2 * q;
        zr[0] = cmul(ssc[2 * q],     unpackA(W, Wm));
        zr[1] = cmul(ssc[2 * q + 1], unpackB(W, Wm));
    }
}

// K5: R = fft_2048( zero-pad(Z row) ); epilogue. First stage folded into load.
template <bool COMPLEX_OUT>
__global__ void __launch_bounds__(512) k5_row_fft_out(const float* __restrict__ nn_out,
                                                      const float* __restrict__ multi_out,
                                                      float* __restrict__ out) {
    __shared__ float2 stw[512];
    __shared__ float2 sbuf[2 * 2048];
    const int row = blockIdx.x;  // 0 .. BATCH*FH-1
    load_tw<512>(stw);
    const float2* Zp = g_Z + (size_t)row * DW;
    for (int j = threadIdx.x; j < DW; j += 512) {
        float2 v = Zp[j];
        sbuf[2 * j]     = v;
        sbuf[2 * j + 1] = v;
    }
    __syncthreads();
    float2* res = stockham_fft4<2048, 1, false, 512, 2>(sbuf, sbuf + 2048, stw);
    const float* ap = nn_out    + (size_t)row * FW;
    const float* mp = multi_out + (size_t)row * FW;
    const float inv = 1.0f / 1.1f;  // 1/(1+RHO)
    if (COMPLEX_OUT) {
        float2* op = (float2*)out + (size_t)row * FW;
        for (int j = threadIdx.x; j < FW; j += 512) {
            float mn = ap[j] - mp[j];
            float2 r = res[j];
            op[j] = make_float2(mn - (mn - r.x) * inv, r.y * inv);
        }
    } else {
        float* op = out + (size_t)row * FW;
        for (int j = threadIdx.x; j < FW; j += 512) {
            float mn = ap[j] - mp[j];
            op[j] = mn - (mn - res[j].x) * inv;
        }
    }
}

extern "C" void kernel_launch(void* const* d_in, const int* in_sizes, int n_in,
                              void* d_out, int out_size) {
    // Input identification, unit-agnostic: frame tensors are 4x the data tensors.
    const float* frames[4] = {0, 0, 0, 0};
    const float* datas[4]  = {0, 0, 0, 0};
    int nf = 0, nd = 0;
    int first_is_frame = 0;
    long long mx = 0, mn = 0x7fffffffffffffffLL;
    for (int i = 0; i < n_in; i++) {
        long long s = in_sizes[i];
        if (s > mx) mx = s;
        if (s < mn) mn = s;
    }
    int ok = (n_in == 4) && (mx == 4 * mn) && (mn > 0);
    if (ok) {
        for (int i = 0; i < 4; i++) {
            if ((long long)in_sizes[i] == mx) { if (i == 0) first_is_frame = 1; if (nf < 4) frames[nf++] = (const float*)d_in[i]; }
            else if ((long long)in_sizes[i] == mn) { if (nd < 4) datas[nd++] = (const float*)d_in[i]; }
        }
        ok = (nf == 2 && nd == 2);
    }

    long long osz = out_size;
    bool complex_out = (osz == 2LL * BATCH * FH * FW) || (osz == 8LL * BATCH * FH * FW);

    if (!ok) {
        long long n = (long long)BATCH * FH * FW;
        zero_fill_kernel<<<(int)((n + 511) / 512), 512>>>((float*)d_out, n);
        return;
    }

    const float* input  = datas[0];
    const float* nn_in  = datas[1];
    const float* nn_out = first_is_frame ? frames[0] : frames[1];  // dict vs alphabetical
    const float* multi  = first_is_frame ? frames[1] : frames[0];

    const size_t smem_k4 = (size_t)(512 + 2 * 2 * 2048) * sizeof(float2);  // 69632 B
    cudaFuncSetAttribute(k4_col_ifft, cudaFuncAttributeMaxDynamicSharedMemorySize, (int)smem_k4);

    twiddle_init_kernel<<<2, 256>>>();
    k1_row_ifft<<<BATCH * DH / 2, 256>>>(nn_in);
    k2_col_fft_dot<<<BATCH * (DW / 4), 256>>>(input);
    k4_col_ifft<<<BATCH * (DW / 4), 256, smem_k4>>>(input);
    if (complex_out)
        k5_row_fft_out<true><<<BATCH * FH, 512>>>(nn_out, multi, (float*)d_out);
    else
        k5_row_fft_out<false><<<BATCH * FH, 512>>>(nn_out, multi, (float*)d_out);
}

// round 7
// speedup vs baseline: 2.9279x; 1.3020x over previous
#include <cuda_runtime.h>

#define BATCH 4
#define DH 1024
#define DW 1024
#define FH 2048
#define FW 2048
#define RT2 0.70710678118654752f

// Scratch (device globals — no allocations allowed in kernel_launch)
__device__ float2 g_Y[BATCH * DH * DW];   // ifft_w(nnline_input)              32 MB
__device__ float2 g_Z[BATCH * FH * DW];   // ifft_h,2048(input * s)            64 MB
__device__ float2 g_S[BATCH * DW];        // per-column unit phase * 1/FH
__device__ float2 g_TW[512];              // tw[j] = e^{-2pi i j/2048}, j<512

__device__ __forceinline__ float2 cmul(float2 a, float2 b) {
    return make_float2(a.x * b.x - a.y * b.y, a.x * b.y + a.y * b.x);
}
__device__ __forceinline__ float2 cadd(float2 a, float2 b) { return make_float2(a.x + b.x, a.y + b.y); }
__device__ __forceinline__ float2 csub(float2 a, float2 b) { return make_float2(a.x - b.x, a.y - b.y); }
// multiply by -i (fwd) / +i (inv)
template <bool INV> __device__ __forceinline__ float2 cmuli(float2 z) {
    return INV ? make_float2(-z.y, z.x) : make_float2(z.y, -z.x);
}
// multiply by w8 = e^{∓2pi i/8}
template <bool INV> __device__ __forceinline__ float2 cmulw8(float2 z) {
    return INV ? make_float2(RT2 * (z.x - z.y), RT2 * (z.y + z.x))
               : make_float2(RT2 * (z.x + z.y), RT2 * (z.y - z.x));
}
// multiply by w8^3 = e^{∓6pi i/8}
template <bool INV> __device__ __forceinline__ float2 cmulw83(float2 z) {
    return INV ? make_float2(-RT2 * (z.x + z.y), RT2 * (z.x - z.y))
               : make_float2(RT2 * (z.y - z.x), -RT2 * (z.x + z.y));
}

__global__ void twiddle_init_kernel() {
    int j = blockIdx.x * blockDim.x + threadIdx.x;
    if (j < 512) {
        float s, c;
        sincospif(j * (1.0f / 1024.0f), &s, &c);   // pi*j/1024 = 2pi*j/2048
        g_TW[j] = make_float2(c, -s);
    }
}

__global__ void zero_fill_kernel(float* p, long long n) {
    long long i = (long long)blockIdx.x * blockDim.x + threadIdx.x;
    if (i < n) p[i] = 0.0f;
}

template <int NT>
__device__ __forceinline__ void load_tw(float2* stw) {
    for (int i = threadIdx.x; i < 512; i += NT) stw[i] = g_TW[i];
}

// ---- Stockham stages.  Layout buf[point*NCOL + col].  tw[j]=e^{-2pi i j/2048}.
// Invariant: dst[R(j-k)+k+r*p] = DFT_R(a_q * w^q)_r,  w = e^{∓2pi i k/(R p)}.

// radix-2, p=1 (twiddle-free)
template <int N, int NCOL, int NT>
__device__ __forceinline__ void r2_stage_p1(const float2* src, float2* dst) {
    constexpr int NB = (N / 2) * NCOL;
#pragma unroll
    for (int u = 0; u < NB / NT; u++) {
        int it = threadIdx.x + u * NT;
        int c = (NCOL == 1) ? 0 : (it & (NCOL - 1));
        int j = (NCOL == 1) ? it : (it / NCOL);
        float2 a = src[it];
        float2 b = src[it + NB];
        dst[(2 * j) * NCOL + c]     = cadd(a, b);
        dst[(2 * j + 1) * NCOL + c] = csub(a, b);
    }
    __syncthreads();
}

// radix-8, generic stage P>=2
template <int N, int NCOL, bool INV, int NT, int P>
__device__ __forceinline__ void r8_stage(const float2* src, float2* dst, const float2* tw) {
    constexpr int S = (N / 8) * NCOL;
#pragma unroll
    for (int u = 0; u < S / NT; u++) {
        int it = threadIdx.x + u * NT;
        int c = (NCOL == 1) ? 0 : (it & (NCOL - 1));
        int j = (NCOL == 1) ? it : (it / NCOL);
        int k = j & (P - 1);
        float2 a0 = src[it];
        float2 a1 = src[it + S];
        float2 a2 = src[it + 2 * S];
        float2 a3 = src[it + 3 * S];
        float2 a4 = src[it + 4 * S];
        float2 a5 = src[it + 5 * S];
        float2 a6 = src[it + 6 * S];
        float2 a7 = src[it + 7 * S];
        float2 w1 = tw[k * (256 / P)];
        if (INV) w1.y = -w1.y;
        float2 w2 = cmul(w1, w1), w3 = cmul(w2, w1), w4 = cmul(w2, w2);
        float2 w5 = cmul(w4, w1), w6 = cmul(w4, w2), w7 = cmul(w4, w3);
        a1 = cmul(a1, w1); a2 = cmul(a2, w2); a3 = cmul(a3, w3); a4 = cmul(a4, w4);
        a5 = cmul(a5, w5); a6 = cmul(a6, w6); a7 = cmul(a7, w7);
        // E = DFT4(a0,a2,a4,a6), O = DFT4(a1,a3,a5,a7)
        float2 sE0 = cadd(a0, a4), sE1 = csub(a0, a4), sE2 = cadd(a2, a6), sE3 = csub(a2, a6);
        float2 E0 = cadd(sE0, sE2), E2 = csub(sE0, sE2);
        float2 E1 = cadd(sE1, cmuli<INV>(sE3)), E3 = csub(sE1, cmuli<INV>(sE3));
        float2 sO0 = cadd(a1, a5), sO1 = csub(a1, a5), sO2 = cadd(a3, a7), sO3 = csub(a3, a7);
        float2 O0 = cadd(sO0, sO2), O2 = csub(sO0, sO2);
        float2 O1 = cadd(sO1, cmuli<INV>(sO3)), O3 = csub(sO1, cmuli<INV>(sO3));
        float2 t0 = O0, t1 = cmulw8<INV>(O1), t2 = cmuli<INV>(O2), t3 = cmulw83<INV>(O3);
        int base = (((j - k) << 3) + k) * NCOL + c;
        dst[base]                = cadd(E0, t0);
        dst[base + P * NCOL]     = cadd(E1, t1);
        dst[base + 2 * P * NCOL] = cadd(E2, t2);
        dst[base + 3 * P * NCOL] = cadd(E3, t3);
        dst[base + 4 * P * NCOL] = csub(E0, t0);
        dst[base + 5 * P * NCOL] = csub(E1, t1);
        dst[base + 6 * P * NCOL] = csub(E2, t2);
        dst[base + 7 * P * NCOL] = csub(E3, t3);
    }
    __syncthreads();
}

// radix-8, p=1, upper half of input is zero (zero-padded transform).
// src holds N/2 valid points in natural order; a4..a7 are implicitly 0; w=1.
template <int N, int NCOL, bool INV, int NT>
__device__ __forceinline__ void r8_stage_zpad(const float2* src, float2* dst) {
    constexpr int S = (N / 8) * NCOL;
#pragma unroll
    for (int u = 0; u < S / NT; u++) {
        int it = threadIdx.x + u * NT;
        int c = (NCOL == 1) ? 0 : (it & (NCOL - 1));
        int j = (NCOL == 1) ? it : (it / NCOL);
        float2 a0 = src[it];
        float2 a1 = src[it + S];
        float2 a2 = src[it + 2 * S];
        float2 a3 = src[it + 3 * S];
        // E = DFT4(a0,a2,0,0), O = DFT4(a1,a3,0,0)
        float2 E0 = cadd(a0, a2), E2 = csub(a0, a2);
        float2 E1 = cadd(a0, cmuli<INV>(a2)), E3 = csub(a0, cmuli<INV>(a2));
        float2 O0 = cadd(a1, a3), O2 = csub(a1, a3);
        float2 O1 = cadd(a1, cmuli<INV>(a3)), O3 = csub(a1, cmuli<INV>(a3));
        float2 t0 = O0, t1 = cmulw8<INV>(O1), t2 = cmuli<INV>(O2), t3 = cmulw83<INV>(O3);
        int base = (j << 3) * NCOL + c;
        dst[base]            = cadd(E0, t0);
        dst[base + NCOL]     = cadd(E1, t1);
        dst[base + 2 * NCOL] = cadd(E2, t2);
        dst[base + 3 * NCOL] = cadd(E3, t3);
        dst[base + 4 * NCOL] = csub(E0, t0);
        dst[base + 5 * NCOL] = csub(E1, t1);
        dst[base + 6 * NCOL] = csub(E2, t2);
        dst[base + 7 * NCOL] = csub(E3, t3);
    }
    __syncthreads();
}

// radix-4, generic stage
template <int N, int NCOL, bool INV, int NT, int P>
__device__ __forceinline__ void r4_stage(const float2* src, float2* dst, const float2* tw) {
    constexpr int S = (N / 4) * NCOL;
#pragma unroll
    for (int u = 0; u < S / NT; u++) {
        int it = threadIdx.x + u * NT;
        int c = (NCOL == 1) ? 0 : (it & (NCOL - 1));
        int j = (NCOL == 1) ? it : (it / NCOL);
        int k = j & (P - 1);
        float2 a0 = src[it];
        float2 a1 = src[it + S];
        float2 a2 = src[it + 2 * S];
        float2 a3 = src[it + 3 * S];
        float2 w1 = tw[k * (512 / P)];
        if (INV) w1.y = -w1.y;
        float2 w2 = cmul(w1, w1), w3 = cmul(w2, w1);
        a1 = cmul(a1, w1); a2 = cmul(a2, w2); a3 = cmul(a3, w3);
        float2 s0 = cadd(a0, a2), s1 = csub(a0, a2), s2 = cadd(a1, a3), s3 = csub(a1, a3);
        int base = (((j - k) << 2) + k) * NCOL + c;
        dst[base]                = cadd(s0, s2);
        dst[base + P * NCOL]     = cadd(s1, cmuli<INV>(s3));
        dst[base + 2 * P * NCOL] = csub(s0, s2);
        dst[base + 3 * P * NCOL] = csub(s1, cmuli<INV>(s3));
    }
    __syncthreads();
}

// N=1024 chain: r2(1), r8(2), r8(16), r8(128). Result lands back in buf0.
template <int NCOL, bool INV, int NT>
__device__ __forceinline__ void fft1024(float2* buf0, float2* buf1, const float2* tw) {
    r2_stage_p1<1024, NCOL, NT>(buf0, buf1);
    r8_stage<1024, NCOL, INV, NT, 2>(buf1, buf0, tw);
    r8_stage<1024, NCOL, INV, NT, 16>(buf0, buf1, tw);
    r8_stage<1024, NCOL, INV, NT, 128>(buf1, buf0, tw);
}

// N=2048 zero-padded chain: r8zpad(1), r8(8), r8(64), r4(512). Result in buf0.
template <int NCOL, bool INV, int NT>
__device__ __forceinline__ void fft2048_zpad(float2* buf0, float2* buf1, const float2* tw) {
    r8_stage_zpad<2048, NCOL, INV, NT>(buf0, buf1);
    r8_stage<2048, NCOL, INV, NT, 8>(buf1, buf0, tw);
    r8_stage<2048, NCOL, INV, NT, 64>(buf0, buf1, tw);
    r4_stage<2048, NCOL, INV, NT, 512>(buf1, buf0, tw);
}

// Hermitian unpack: W = transform(xa + i*xb), xa,xb real.
__device__ __forceinline__ float2 unpackA(float2 W, float2 Wm) {
    return make_float2(0.5f * (W.x + Wm.x), 0.5f * (W.y - Wm.y));
}
__device__ __forceinline__ float2 unpackB(float2 W, float2 Wm) {
    return make_float2(0.5f * (W.y + Wm.y), 0.5f * (Wm.x - W.x));
}

// K1: 4 real rows per block, packed as 2 complex ifft_1024 (NCOL=2).
__global__ void __launch_bounds__(256) k1_row_ifft(const float* __restrict__ nn_in) {
    __shared__ float2 stw[512];
    __shared__ float2 buf0[2048];
    __shared__ float2 buf1[2048];
    const int row0 = 4 * blockIdx.x;
    load_tw<256>(stw);
    const float* base = nn_in + (size_t)row0 * DW;
#pragma unroll
    for (int u = 0; u < 8; u++) {
        int it = threadIdx.x + u * 256;
        int c = it >> 10, h = it & 1023;
        buf0[h * 2 + c] = make_float2(base[(size_t)(2 * c) * DW + h] * (1.0f / DW),
                                      base[(size_t)(2 * c + 1) * DW + h] * (1.0f / DW));
    }
    __syncthreads();
    fft1024<2, true, 256>(buf0, buf1, stw);
    float2* outp = g_Y + (size_t)row0 * DW;
#pragma unroll
    for (int u = 0; u < 4; u++) {
        int j = threadIdx.x + u * 256;
        int jm = (1024 - j) & 1023;
#pragma unroll
        for (int c = 0; c < 2; c++) {
            float2 W = buf0[j * 2 + c], Wm = buf0[jm * 2 + c];
            outp[(size_t)(2 * c) * DW + j]     = unpackA(W, Wm);
            outp[(size_t)(2 * c + 1) * DW + j] = unpackB(W, Wm);
        }
    }
}

// K2: X = fft_1024(input cols, 2 real cols packed); T[w] = sum_m Y[m,w]*X[m,w];
// tmp = conj(T); scale = (-T.y + i*T.x)/|T| * (1/FH).
__global__ void __launch_bounds__(256) k2_col_fft_dot(const float* __restrict__ input) {
    __shared__ float2 stw[512];
    __shared__ float2 buf0[2048];
    __shared__ float2 buf1[2048];
    const int bg = blockIdx.x;
    const int b  = bg >> 8;
    const int w0 = (bg & 255) << 2;
    load_tw<256>(stw);
    const float* Xp = input + (size_t)b * DH * DW + w0;
#pragma unroll
    for (int u = 0; u < 8; u++) {
        int it = threadIdx.x + u * 256;
        int q = it & 1, h = it >> 1;
        buf0[h * 2 + q] = *(const float2*)(Xp + (size_t)h * DW + 2 * q);
    }
    __syncthreads();
    fft1024<2, false, 256>(buf0, buf1, stw);   // result in buf0
    float2* part = buf1;

    const float2* Yp = g_Y + (size_t)b * DH * DW + w0;
    const int c = threadIdx.x & 3;
    const int q = c >> 1, e = c & 1;
    float2 acc = make_float2(0.0f, 0.0f);
    for (int m = threadIdx.x >> 2; m < DH; m += 64) {
        int mm = (1024 - m) & 1023;
        float2 W = buf0[m * 2 + q], Wm = buf0[mm * 2 + q];
        float2 X = e ? unpackB(W, Wm) : unpackA(W, Wm);
        float2 Yv = Yp[(size_t)m * DW + c];
        acc.x += Yv.x * X.x - Yv.y * X.y;
        acc.y += Yv.x * X.y + Yv.y * X.x;
    }
    __syncthreads();
    part[threadIdx.x] = acc;
    __syncthreads();
    for (int s = 128; s >= 4; s >>= 1) {
        if (threadIdx.x < s) {
            part[threadIdx.x].x += part[threadIdx.x + s].x;
            part[threadIdx.x].y += part[threadIdx.x + s].y;
        }
        __syncthreads();
    }
    if (threadIdx.x < 4) {
        float2 T = part[threadIdx.x];
        float r  = sqrtf(T.x * T.x + T.y * T.y);
        float2 sc = (r > 0.0f) ? make_float2(-T.y / r, T.x / r) : make_float2(1.0f, 0.0f);
        g_S[b * DW + w0 + threadIdx.x] = make_float2(sc.x * (1.0f / FH), sc.y * (1.0f / FH));
    }
}

// K4: 4 cols as 2 packed real ifft_2048 (zero-padding consumed by first stage).
// Phase scale s applied AFTER Hermitian unpack.
__global__ void __launch_bounds__(256) k4_col_ifft(const float* __restrict__ input) {
    extern __shared__ float2 sm[];
    float2* stw  = sm;                 // 512
    float2* buf0 = sm + 512;           // 2048*2
    float2* buf1 = buf0 + 2048 * 2;    // 2048*2
    __shared__ float2 ssc[4];
    const int bg = blockIdx.x;
    const int b  = bg >> 8;
    const int w0 = (bg & 255) << 2;
    load_tw<256>(stw);
    if (threadIdx.x < 4) ssc[threadIdx.x] = g_S[b * DW + w0 + threadIdx.x];
    __syncthreads();
    const float* Xp = input + (size_t)b * DH * DW + w0;
#pragma unroll
    for (int u = 0; u < 8; u++) {     // only lower 1024 points are nonzero
        int it = threadIdx.x + u * 256;
        int q = it & 1, h = it >> 1;
        buf0[h * 2 + q] = *(const float2*)(Xp + (size_t)h * DW + 2 * q);
    }
    __syncthreads();
    fft2048_zpad<2, true, 256>(buf0, buf1, stw);   // result in buf0
    float2* Zp = g_Z + (size_t)b * FH * DW + w0;
#pragma unroll
    for (int u = 0; u < 16; u++) {
        int it = threadIdx.x + u * 256;
        int q = it & 1, m = it >> 1;
        int mm = (2048 - m) & 2047;
        float2 W = buf0[m * 2 + q], Wm = buf0[mm * 2 + q];
        float2* zr = Zp + (size_t)m * DW + 2 * q;
        zr[0] = cmul(ssc[2 * q],     unpackA(W, Wm));
        zr[1] = cmul(ssc[2 * q + 1], unpackB(W, Wm));
    }
}

// K5: R = fft_2048( zero-pad(Z row) ); epilogue.
template <bool COMPLEX_OUT>
__global__ void __launch_bounds__(256) k5_row_fft_out(const float* __restrict__ nn_out,
                                                      const float* __restrict__ multi_out,
                                                      float* __restrict__ out) {
    __shared__ float2 stw[512];
    __shared__ float2 buf0[2048];
    __shared__ float2 buf1[2048];
    const int row = blockIdx.x;  // 0 .. BATCH*FH-1
    load_tw<256>(stw);
    const float2* Zp = g_Z + (size_t)row * DW;
#pragma unroll
    for (int u = 0; u < 4; u++) {
        int j = threadIdx.x + u * 256;
        buf0[j] = Zp[j];
    }
    __syncthreads();
    fft2048_zpad<1, false, 256>(buf0, buf1, stw);  // result in buf0
    const float* ap = nn_out    + (size_t)row * FW;
    const float* mp = multi_out + (size_t)row * FW;
    const float inv = 1.0f / 1.1f;  // 1/(1+RHO)
    if (COMPLEX_OUT) {
        float2* op = (float2*)out + (size_t)row * FW;
#pragma unroll
        for (int u = 0; u < 8; u++) {
            int j = threadIdx.x + u * 256;
            float mn = ap[j] - mp[j];
            float2 r = buf0[j];
            op[j] = make_float2(mn - (mn - r.x) * inv, r.y * inv);
        }
    } else {
        float* op = out + (size_t)row * FW;
#pragma unroll
        for (int u = 0; u < 8; u++) {
            int j = threadIdx.x + u * 256;
            float mn = ap[j] - mp[j];
            op[j] = mn - (mn - buf0[j].x) * inv;
        }
    }
}

extern "C" void kernel_launch(void* const* d_in, const int* in_sizes, int n_in,
                              void* d_out, int out_size) {
    // Input identification, unit-agnostic: frame tensors are 4x the data tensors.
    const float* frames[4] = {0, 0, 0, 0};
    const float* datas[4]  = {0, 0, 0, 0};
    int nf = 0, nd = 0;
    int first_is_frame = 0;
    long long mx = 0, mn = 0x7fffffffffffffffLL;
    for (int i = 0; i < n_in; i++) {
        long long s = in_sizes[i];
        if (s > mx) mx = s;
        if (s < mn) mn = s;
    }
    int ok = (n_in == 4) && (mx == 4 * mn) && (mn > 0);
    if (ok) {
        for (int i = 0; i < 4; i++) {
            if ((long long)in_sizes[i] == mx) { if (i == 0) first_is_frame = 1; if (nf < 4) frames[nf++] = (const float*)d_in[i]; }
            else if ((long long)in_sizes[i] == mn) { if (nd < 4) datas[nd++] = (const float*)d_in[i]; }
        }
        ok = (nf == 2 && nd == 2);
    }

    long long osz = out_size;
    bool complex_out = (osz == 2LL * BATCH * FH * FW) || (osz == 8LL * BATCH * FH * FW);

    if (!ok) {
        long long n = (long long)BATCH * FH * FW;
        zero_fill_kernel<<<(int)((n + 511) / 512), 512>>>((float*)d_out, n);
        return;
    }

    const float* input  = datas[0];
    const float* nn_in  = datas[1];
    const float* nn_out = first_is_frame ? frames[0] : frames[1];  // dict vs alphabetical
    const float* multi  = first_is_frame ? frames[1] : frames[0];

    const size_t smem_k4 = (size_t)(512 + 2 * 2 * 2048) * sizeof(float2);  // 69632 B
    cudaFuncSetAttribute(k4_col_ifft, cudaFuncAttributeMaxDynamicSharedMemorySize, (int)smem_k4);

    twiddle_init_kernel<<<2, 256>>>();
    k1_row_ifft<<<BATCH * DH / 4, 256>>>(nn_in);
    k2_col_fft_dot<<<BATCH * (DW / 4), 256>>>(input);
    k4_col_ifft<<<BATCH * (DW / 4), 256, smem_k4>>>(input);
    if (complex_out)
        k5_row_fft_out<true><<<BATCH * FH, 256>>>(nn_out, multi, (float*)d_out);
    else
        k5_row_fft_out<false><<<BATCH * FH, 256>>>(nn_out, multi, (float*)d_out);
}

// round 8
// speedup vs baseline: 3.3769x; 1.1534x over previous
#include <cuda_runtime.h>

#define BATCH 4
#define DH 1024
#define DW 1024
#define FH 2048
#define FW 2048
#define RT2 0.70710678118654752f

// Scratch (device globals — no allocations allowed in kernel_launch)
__device__ float2 g_Y[BATCH * DH * DW];   // ifft_w(nnline_input)              32 MB
__device__ float2 g_Z[BATCH * FH * DW];   // ifft_h,2048(input * s)            64 MB
__device__ float2 g_S[BATCH * DW];        // per-column unit phase * 1/FH
__device__ float2 g_TW[512];              // tw[j] = e^{-2pi i j/2048}, j<512

__device__ __forceinline__ float2 cmul(float2 a, float2 b) {
    return make_float2(a.x * b.x - a.y * b.y, a.x * b.y + a.y * b.x);
}
__device__ __forceinline__ float2 cadd(float2 a, float2 b) { return make_float2(a.x + b.x, a.y + b.y); }
__device__ __forceinline__ float2 csub(float2 a, float2 b) { return make_float2(a.x - b.x, a.y - b.y); }
// multiply by -i (fwd) / +i (inv)
template <bool INV> __device__ __forceinline__ float2 cmuli(float2 z) {
    return INV ? make_float2(-z.y, z.x) : make_float2(z.y, -z.x);
}
// multiply by w8 = e^{∓2pi i/8}
template <bool INV> __device__ __forceinline__ float2 cmulw8(float2 z) {
    return INV ? make_float2(RT2 * (z.x - z.y), RT2 * (z.y + z.x))
               : make_float2(RT2 * (z.x + z.y), RT2 * (z.y - z.x));
}
// multiply by w8^3
template <bool INV> __device__ __forceinline__ float2 cmulw83(float2 z) {
    return INV ? make_float2(-RT2 * (z.x + z.y), RT2 * (z.x - z.y))
               : make_float2(RT2 * (z.y - z.x), -RT2 * (z.x + z.y));
}

__global__ void twiddle_init_kernel() {
    int j = blockIdx.x * blockDim.x + threadIdx.x;
    if (j < 512) {
        float s, c;
        sincospif(j * (1.0f / 1024.0f), &s, &c);
        g_TW[j] = make_float2(c, -s);
    }
}

__global__ void zero_fill_kernel(float* p, long long n) {
    long long i = (long long)blockIdx.x * blockDim.x + threadIdx.x;
    if (i < n) p[i] = 0.0f;
}

template <int NT>
__device__ __forceinline__ void load_tw(float2* stw) {
    for (int i = threadIdx.x; i < 512; i += NT) stw[i] = g_TW[i];
}

// ---- In-place Stockham stages. Layout buf[point*NCOL + col]. tw[j]=e^{-2pi i j/2048}.
// Invariant: dst[R(j-k)+k+r*p] = DFT_R(a_q * w^q)_r,  w = e^{∓2pi i k/(R p)}.
// Read-all -> barrier -> write-all -> barrier (single buffer).

template <bool INV>
__device__ __forceinline__ void dft8(float2 a0, float2 a1, float2 a2, float2 a3,
                                     float2 a4, float2 a5, float2 a6, float2 a7,
                                     float2* o) {
    float2 sE0 = cadd(a0, a4), sE1 = csub(a0, a4), sE2 = cadd(a2, a6), sE3 = csub(a2, a6);
    float2 E0 = cadd(sE0, sE2), E2 = csub(sE0, sE2);
    float2 E1 = cadd(sE1, cmuli<INV>(sE3)), E3 = csub(sE1, cmuli<INV>(sE3));
    float2 sO0 = cadd(a1, a5), sO1 = csub(a1, a5), sO2 = cadd(a3, a7), sO3 = csub(a3, a7);
    float2 O0 = cadd(sO0, sO2), O2 = csub(sO0, sO2);
    float2 O1 = cadd(sO1, cmuli<INV>(sO3)), O3 = csub(sO1, cmuli<INV>(sO3));
    float2 t0 = O0, t1 = cmulw8<INV>(O1), t2 = cmuli<INV>(O2), t3 = cmulw83<INV>(O3);
    o[0] = cadd(E0, t0); o[1] = cadd(E1, t1); o[2] = cadd(E2, t2); o[3] = cadd(E3, t3);
    o[4] = csub(E0, t0); o[5] = csub(E1, t1); o[6] = csub(E2, t2); o[7] = csub(E3, t3);
}

template <int N, int NCOL, bool INV, int NT, int P>
__device__ __forceinline__ void r8_ip(float2* buf, const float2* tw) {
    constexpr int S = (N / 8) * NCOL;
    constexpr int U = S / NT;
    float2 v[U][8];
#pragma unroll
    for (int u = 0; u < U; u++) {
        int it = threadIdx.x + u * NT;
#pragma unroll
        for (int q = 0; q < 8; q++) v[u][q] = buf[it + q * S];
    }
    __syncthreads();
#pragma unroll
    for (int u = 0; u < U; u++) {
        int it = threadIdx.x + u * NT;
        int c = (NCOL == 1) ? 0 : (it & (NCOL - 1));
        int j = (NCOL == 1) ? it : (it / NCOL);
        int k = j & (P - 1);
        float2 w1 = tw[k * (256 / P)];
        if (INV) w1.y = -w1.y;
        float2 w2 = cmul(w1, w1), w3 = cmul(w2, w1), w4 = cmul(w2, w2);
        float2 w5 = cmul(w4, w1), w6 = cmul(w4, w2), w7 = cmul(w4, w3);
        float2 o[8];
        dft8<INV>(v[u][0], cmul(v[u][1], w1), cmul(v[u][2], w2), cmul(v[u][3], w3),
                  cmul(v[u][4], w4), cmul(v[u][5], w5), cmul(v[u][6], w6), cmul(v[u][7], w7), o);
        int base = (((j - k) << 3) + k) * NCOL + c;
#pragma unroll
        for (int r = 0; r < 8; r++) buf[base + r * P * NCOL] = o[r];
    }
    __syncthreads();
}

template <int N, int NCOL, bool INV, int NT, int P>
__device__ __forceinline__ void r4_ip(float2* buf, const float2* tw) {
    constexpr int S = (N / 4) * NCOL;
    constexpr int U = S / NT;
    float2 v[U][4];
#pragma unroll
    for (int u = 0; u < U; u++) {
        int it = threadIdx.x + u * NT;
#pragma unroll
        for (int q = 0; q < 4; q++) v[u][q] = buf[it + q * S];
    }
    __syncthreads();
#pragma unroll
    for (int u = 0; u < U; u++) {
        int it = threadIdx.x + u * NT;
        int c = (NCOL == 1) ? 0 : (it & (NCOL - 1));
        int j = (NCOL == 1) ? it : (it / NCOL);
        int k = j & (P - 1);
        float2 w1 = tw[k * (512 / P)];
        if (INV) w1.y = -w1.y;
        float2 w2 = cmul(w1, w1), w3 = cmul(w2, w1);
        float2 a0 = v[u][0], a1 = cmul(v[u][1], w1), a2 = cmul(v[u][2], w2), a3 = cmul(v[u][3], w3);
        float2 s0 = cadd(a0, a2), s1 = csub(a0, a2), s2 = cadd(a1, a3), s3 = csub(a1, a3);
        int base = (((j - k) << 2) + k) * NCOL + c;
        buf[base]                = cadd(s0, s2);
        buf[base + P * NCOL]     = cadd(s1, cmuli<INV>(s3));
        buf[base + 2 * P * NCOL] = csub(s0, s2);
        buf[base + 3 * P * NCOL] = csub(s1, cmuli<INV>(s3));
    }
    __syncthreads();
}

// First stage of zero-padded 2048 transform, fused with gmem load: radix-8, p=1,
// upper half zero (a4..a7 = 0), twiddle-free. a_q = point j + q*256 (q<4).
template <bool INV>
__device__ __forceinline__ void dft8_zpad(float2 a0, float2 a1, float2 a2, float2 a3, float2* o) {
    float2 E0 = cadd(a0, a2), E2 = csub(a0, a2);
    float2 E1 = cadd(a0, cmuli<INV>(a2)), E3 = csub(a0, cmuli<INV>(a2));
    float2 O0 = cadd(a1, a3), O2 = csub(a1, a3);
    float2 O1 = cadd(a1, cmuli<INV>(a3)), O3 = csub(a1, cmuli<INV>(a3));
    float2 t0 = O0, t1 = cmulw8<INV>(O1), t2 = cmuli<INV>(O2), t3 = cmulw83<INV>(O3);
    o[0] = cadd(E0, t0); o[1] = cadd(E1, t1); o[2] = cadd(E2, t2); o[3] = cadd(E3, t3);
    o[4] = csub(E0, t0); o[5] = csub(E1, t1); o[6] = csub(E2, t2); o[7] = csub(E3, t3);
}

// Hermitian unpack: W = transform(xa + i*xb), xa,xb real.
__device__ __forceinline__ float2 unpackA(float2 W, float2 Wm) {
    return make_float2(0.5f * (W.x + Wm.x), 0.5f * (W.y - Wm.y));
}
__device__ __forceinline__ float2 unpackB(float2 W, float2 Wm) {
    return make_float2(0.5f * (W.y + Wm.y), 0.5f * (Wm.x - W.x));
}

// K1: 4 real rows per block packed as 2 complex ifft_1024 (NCOL=2).
// Chain: fused r2(p=1) from gmem, then in-place r8(2), r8(16), r8(128).
__global__ void __launch_bounds__(256) k1_row_ifft(const float* __restrict__ nn_in) {
    __shared__ float2 stw[512];
    __shared__ float2 buf[2048];
    const int row0 = 4 * blockIdx.x;
    load_tw<256>(stw);
    const float* basep = nn_in + (size_t)row0 * DW;
#pragma unroll
    for (int u = 0; u < 4; u++) {
        int it = threadIdx.x + u * 256;
        int c = it & 1, j = it >> 1;
        const float* rA = basep + (size_t)(2 * c) * DW;
        const float* rB = basep + (size_t)(2 * c + 1) * DW;
        float2 a = make_float2(rA[j] * (1.0f / DW), rB[j] * (1.0f / DW));
        float2 b = make_float2(rA[j + 512] * (1.0f / DW), rB[j + 512] * (1.0f / DW));
        buf[(2 * j) * 2 + c]     = cadd(a, b);
        buf[(2 * j + 1) * 2 + c] = csub(a, b);
    }
    __syncthreads();
    r8_ip<1024, 2, true, 256, 2>(buf, stw);
    r8_ip<1024, 2, true, 256, 16>(buf, stw);
    r8_ip<1024, 2, true, 256, 128>(buf, stw);
    float2* outp = g_Y + (size_t)row0 * DW;
#pragma unroll
    for (int u = 0; u < 4; u++) {
        int j = threadIdx.x + u * 256;
        int jm = (1024 - j) & 1023;
#pragma unroll
        for (int c = 0; c < 2; c++) {
            float2 W = buf[j * 2 + c], Wm = buf[jm * 2 + c];
            outp[(size_t)(2 * c) * DW + j]     = unpackA(W, Wm);
            outp[(size_t)(2 * c + 1) * DW + j] = unpackB(W, Wm);
        }
    }
}

// K2: X = fft_1024(input cols, 2 real cols packed); T[w] = sum_m Y[m,w]*X[m,w];
// scale = (-T.y + i*T.x)/|T| * (1/FH).
__global__ void __launch_bounds__(256) k2_col_fft_dot(const float* __restrict__ input) {
    __shared__ float2 stw[512];
    __shared__ float2 buf[2048];
    const int bg = blockIdx.x;
    const int b  = bg >> 8;
    const int w0 = (bg & 255) << 2;
    load_tw<256>(stw);
    const float* Xp = input + (size_t)b * DH * DW + w0;
#pragma unroll
    for (int u = 0; u < 4; u++) {
        int it = threadIdx.x + u * 256;
        int c = it & 1, j = it >> 1;
        float2 a = *(const float2*)(Xp + (size_t)j * DW + 2 * c);
        float2 b2 = *(const float2*)(Xp + (size_t)(j + 512) * DW + 2 * c);
        buf[(2 * j) * 2 + c]     = cadd(a, b2);
        buf[(2 * j + 1) * 2 + c] = csub(a, b2);
    }
    __syncthreads();
    r8_ip<1024, 2, false, 256, 2>(buf, stw);
    r8_ip<1024, 2, false, 256, 16>(buf, stw);
    r8_ip<1024, 2, false, 256, 128>(buf, stw);

    const float2* Yp = g_Y + (size_t)b * DH * DW + w0;
    const int c = threadIdx.x & 3;
    const int q = c >> 1, e = c & 1;
    float2 acc = make_float2(0.0f, 0.0f);
    for (int m = threadIdx.x >> 2; m < DH; m += 64) {
        int mm = (1024 - m) & 1023;
        float2 W = buf[m * 2 + q], Wm = buf[mm * 2 + q];
        float2 X = e ? unpackB(W, Wm) : unpackA(W, Wm);
        float2 Yv = Yp[(size_t)m * DW + c];
        acc.x += Yv.x * X.x - Yv.y * X.y;
        acc.y += Yv.x * X.y + Yv.y * X.x;
    }
    __syncthreads();          // all dot reads of buf complete
    buf[threadIdx.x] = acc;   // reuse buf as reduction scratch
    __syncthreads();
    for (int s = 128; s >= 4; s >>= 1) {
        if (threadIdx.x < s) {
            buf[threadIdx.x].x += buf[threadIdx.x + s].x;
            buf[threadIdx.x].y += buf[threadIdx.x + s].y;
        }
        __syncthreads();
    }
    if (threadIdx.x < 4) {
        float2 T = buf[threadIdx.x];
        float r  = sqrtf(T.x * T.x + T.y * T.y);
        float2 sc = (r > 0.0f) ? make_float2(-T.y / r, T.x / r) : make_float2(1.0f, 0.0f);
        g_S[b * DW + w0 + threadIdx.x] = make_float2(sc.x * (1.0f / FH), sc.y * (1.0f / FH));
    }
}

// K4: 4 cols as 2 packed real ifft_2048. Fused zpad-r8(p=1) from gmem,
// then in-place r8(8), r8(64), r4(512). 512 threads.
__global__ void __launch_bounds__(512) k4_col_ifft(const float* __restrict__ input) {
    __shared__ float2 stw[512];
    __shared__ float2 buf[4096];
    __shared__ float2 ssc[4];
    const int bg = blockIdx.x;
    const int b  = bg >> 8;
    const int w0 = (bg & 255) << 2;
    load_tw<512>(stw);
    if (threadIdx.x < 4) ssc[threadIdx.x] = g_S[b * DW + w0 + threadIdx.x];
    const float* Xp = input + (size_t)b * DH * DW + w0;
    {
        int it = threadIdx.x;           // S = 512, U = 1
        int c = it & 1, j = it >> 1;    // j < 256
        float2 a0 = *(const float2*)(Xp + (size_t)j * DW + 2 * c);
        float2 a1 = *(const float2*)(Xp + (size_t)(j + 256) * DW + 2 * c);
        float2 a2 = *(const float2*)(Xp + (size_t)(j + 512) * DW + 2 * c);
        float2 a3 = *(const float2*)(Xp + (size_t)(j + 768) * DW + 2 * c);
        float2 o[8];
        dft8_zpad<true>(a0, a1, a2, a3, o);
        int base = (j << 3) * 2 + c;
#pragma unroll
        for (int r = 0; r < 8; r++) buf[base + r * 2] = o[r];
    }
    __syncthreads();
    r8_ip<2048, 2, true, 512, 8>(buf, stw);
    r8_ip<2048, 2, true, 512, 64>(buf, stw);
    r4_ip<2048, 2, true, 512, 512>(buf, stw);
    float2* Zp = g_Z + (size_t)b * FH * DW + w0;
#pragma unroll
    for (int u = 0; u < 8; u++) {
        int it = threadIdx.x + u * 512;
        int q = it & 1, m = it >> 1;
        int mm = (2048 - m) & 2047;
        float2 W = buf[m * 2 + q], Wm = buf[mm * 2 + q];
        float2* zr = Zp + (size_t)m * DW + 2 * q;
        zr[0] = cmul(ssc[2 * q],     unpackA(W, Wm));
        zr[1] = cmul(ssc[2 * q + 1], unpackB(W, Wm));
    }
}

// K5: R = fft_2048( zero-pad(Z row) ); epilogue. Fused zpad-r8 from gmem.
template <bool COMPLEX_OUT>
__global__ void __launch_bounds__(256) k5_row_fft_out(const float* __restrict__ nn_out,
                                                      const float* __restrict__ multi_out,
                                                      float* __restrict__ out) {
    __shared__ float2 stw[512];
    __shared__ float2 buf[2048];
    const int row = blockIdx.x;  // 0 .. BATCH*FH-1
    load_tw<256>(stw);
    const float2* Zp = g_Z + (size_t)row * DW;
    {
        int j = threadIdx.x;             // S = 256, U = 1
        float2 a0 = Zp[j];
        float2 a1 = Zp[j + 256];
        float2 a2 = Zp[j + 512];
        float2 a3 = Zp[j + 768];
        float2 o[8];
        dft8_zpad<false>(a0, a1, a2, a3, o);
        int base = j << 3;
#pragma unroll
        for (int r = 0; r < 8; r++) buf[base + r] = o[r];
    }
    __syncthreads();
    r8_ip<2048, 1, false, 256, 8>(buf, stw);
    r8_ip<2048, 1, false, 256, 64>(buf, stw);
    r4_ip<2048, 1, false, 256, 512>(buf, stw);
    const float* ap = nn_out    + (size_t)row * FW;
    const float* mp = multi_out + (size_t)row * FW;
    const float inv = 1.0f / 1.1f;  // 1/(1+RHO)
    if (COMPLEX_OUT) {
        float2* op = (float2*)out + (size_t)row * FW;
#pragma unroll
        for (int u = 0; u < 8; u++) {
            int j = threadIdx.x + u * 256;
            float mn = ap[j] - mp[j];
            float2 r = buf[j];
            op[j] = make_float2(mn - (mn - r.x) * inv, r.y * inv);
        }
    } else {
        float* op = out + (size_t)row * FW;
#pragma unroll
        for (int u = 0; u < 8; u++) {
            int j = threadIdx.x + u * 256;
            float mn = ap[j] - mp[j];
            op[j] = mn - (mn - buf[j].x) * inv;
        }
    }
}

extern "C" void kernel_launch(void* const* d_in, const int* in_sizes, int n_in,
                              void* d_out, int out_size) {
    // Input identification, unit-agnostic: frame tensors are 4x the data tensors.
    const float* frames[4] = {0, 0, 0, 0};
    const float* datas[4]  = {0, 0, 0, 0};
    int nf = 0, nd = 0;
    int first_is_frame = 0;
    long long mx = 0, mn = 0x7fffffffffffffffLL;
    for (int i = 0; i < n_in; i++) {
        long long s = in_sizes[i];
        if (s > mx) mx = s;
        if (s < mn) mn = s;
    }
    int ok = (n_in == 4) && (mx == 4 * mn) && (mn > 0);
    if (ok) {
        for (int i = 0; i < 4; i++) {
            if ((long long)in_sizes[i] == mx) { if (i == 0) first_is_frame = 1; if (nf < 4) frames[nf++] = (const float*)d_in[i]; }
            else if ((long long)in_sizes[i] == mn) { if (nd < 4) datas[nd++] = (const float*)d_in[i]; }
        }
        ok = (nf == 2 && nd == 2);
    }

    long long osz = out_size;
    bool complex_out = (osz == 2LL * BATCH * FH * FW) || (osz == 8LL * BATCH * FH * FW);

    if (!ok) {
        long long n = (long long)BATCH * FH * FW;
        zero_fill_kernel<<<(int)((n + 511) / 512), 512>>>((float*)d_out, n);
        return;
    }

    const float* input  = datas[0];
    const float* nn_in  = datas[1];
    const float* nn_out = first_is_frame ? frames[0] : frames[1];  // dict vs alphabetical
    const float* multi  = first_is_frame ? frames[1] : frames[0];

    twiddle_init_kernel<<<2, 256>>>();
    k1_row_ifft<<<BATCH * DH / 4, 256>>>(nn_in);
    k2_col_fft_dot<<<BATCH * (DW / 4), 256>>>(input);
    k4_col_ifft<<<BATCH * (DW / 4), 512>>>(input);
    if (complex_out)
        k5_row_fft_out<true><<<BATCH * FH, 256>>>(nn_out, multi, (float*)d_out);
    else
        k5_row_fft_out<false><<<BATCH * FH, 256>>>(nn_out, multi, (float*)d_out);
}